// round 16
// baseline (speedup 1.0000x reference)
#include <cuda_runtime.h>
#include <cstdint>

// ---------------- static device scratch ----------------
__device__ __align__(16) float g_P[6160384];
__device__ __align__(16) float g_xga[64 * 384];
__device__ __align__(16) float g_oatt[64 * 512];
__device__ __align__(16) float g_attW[64 * 512];
__device__ __align__(16) float g_odec[64 * 1152];
__device__ __align__(16) float g_res1[64 * 512];
__device__ __align__(16) float g_part[64 * 8 * 512];
__device__ __align__(16) float g_wchunk[512];

// partial-region offsets (floats)
#define OFF_P1 0        // pre1:  ns=2,  ldp=512   (KC=64)
#define OFF_P2 65536    // pre2:  ns=8,  ldp=256   (KC=64)
#define OFF_A  196608   // gruA:  ns=12, ldp=1536  (KC=32)
#define OFF_W  1376256  // wdec:  ns=16, ldp=512   (KC=32)
#define OFF_G  1900544  // wsc|g1:ns=18, ldp=2048  (KC=64)
#define OFF_2  4259840  // g2:    ns=16, ldp=1536  (KC=32)
#define OFF_O  5832704  // wout:  ns=16, ldp=160   (KC=32)

__device__ __forceinline__ float tanh_fast(float x) {
    float y; asm("tanh.approx.f32 %0, %1;" : "=f"(y) : "f"(x)); return y;
}
__device__ __forceinline__ float gru_out(float gr, float gz, float gn,
                                         float br, float bz, float bn) {
    float r  = 1.f / (1.f + __expf(-(gr + br)));
    float z  = 1.f / (1.f + __expf(-(gz + bz)));
    float nn = tanhf(gn + r * bn);
    return (1.f - z) * nn;
}
__device__ __forceinline__ void add4(float4& a, const float4 b) {
    a.x += b.x; a.y += b.y; a.z += b.z; a.w += b.w;
}
__device__ __forceinline__ void pdl_trigger() {
#if __CUDA_ARCH__ >= 900
    cudaTriggerProgrammaticLaunchCompletion();
#endif
}
__device__ __forceinline__ void pdl_wait() {
#if __CUDA_ARCH__ >= 900
    cudaGridDependencySynchronize();
#endif
}

// ---------------- X functors ----------------
struct XDirect {
    const float* X; int ldx;
    __device__ __forceinline__ float4 load4(int n, int k) const {
        return *reinterpret_cast<const float4*>(X + (size_t)n * ldx + k);
    }
    __device__ __forceinline__ float load1(int n, int k) const {
        return X[(size_t)n * ldx + k];
    }
};
struct XPre1Red {   // t1 = relu(pb1 + sum of 2 pre1 partials)
    const float* P1; const float* pb1;
    __device__ __forceinline__ float4 load4(int n, int k) const {
        float4 s = *reinterpret_cast<const float4*>(pb1 + k);
#pragma unroll
        for (int sp = 0; sp < 2; sp++)
            add4(s, *reinterpret_cast<const float4*>(P1 + sp * 32768 + n * 512 + k));
        s.x = fmaxf(s.x, 0.f); s.y = fmaxf(s.y, 0.f);
        s.z = fmaxf(s.z, 0.f); s.w = fmaxf(s.w, 0.f);
        return s;
    }
    __device__ __forceinline__ float load1(int n, int k) const {
        float s = pb1[k];
        for (int sp = 0; sp < 2; sp++) s += P1[sp * 32768 + n * 512 + k];
        return fmaxf(s, 0.f);
    }
};
struct XGru2Red {   // res2 = res1 + gru2 from 16 partials (ldp=1536)
    const float* P; const float* bih; const float* bhh; const float* res1;
    __device__ __forceinline__ float4 load4(int n, int k) const {
        const float* b = P + (size_t)n * 1536 + k;
        float4 r = *reinterpret_cast<const float4*>(bih + k);
        float4 z = *reinterpret_cast<const float4*>(bih + 512 + k);
        float4 m = *reinterpret_cast<const float4*>(bih + 1024 + k);
#pragma unroll
        for (int sp = 0; sp < 16; sp++) {
            const float* q = b + (size_t)sp * 98304;
            add4(r, *reinterpret_cast<const float4*>(q));
            add4(z, *reinterpret_cast<const float4*>(q + 512));
            add4(m, *reinterpret_cast<const float4*>(q + 1024));
        }
        float4 br = *reinterpret_cast<const float4*>(bhh + k);
        float4 bz = *reinterpret_cast<const float4*>(bhh + 512 + k);
        float4 bn = *reinterpret_cast<const float4*>(bhh + 1024 + k);
        float4 rv = *reinterpret_cast<const float4*>(res1 + n * 512 + k);
        float4 o;
        o.x = gru_out(r.x, z.x, m.x, br.x, bz.x, bn.x) + rv.x;
        o.y = gru_out(r.y, z.y, m.y, br.y, bz.y, bn.y) + rv.y;
        o.z = gru_out(r.z, z.z, m.z, br.z, bz.z, bn.z) + rv.z;
        o.w = gru_out(r.w, z.w, m.w, br.w, bz.w, bn.w) + rv.w;
        return o;
    }
    __device__ __forceinline__ float load1(int n, int k) const {
        float gr = bih[k], gz = bih[512 + k], gn = bih[1024 + k];
        for (int sp = 0; sp < 16; sp++) {
            const float* q = P + (size_t)sp * 98304 + (size_t)n * 1536 + k;
            gr += q[0]; gz += q[512]; gn += q[1024];
        }
        return gru_out(gr, gz, gn, bhh[k], bhh[512 + k], bhh[1024 + k]) + res1[n * 512 + k];
    }
};

// ---------------- k-split GEMM: 256 threads, tile 64j x 64n, thread 4j x 4n ----------------
// PDL: W gather (independent) first, trigger at entry, wait before X gather.
struct GW {
    const float* W1; int m1; const float* W2; int ldw;
    int kjump_at, kjump_ofs, M, K, jt_n;
    float* P; int ldp;
};

template <int KC, class XF>
__global__ __launch_bounds__(256) void k_gemm(const XF xf, const GW g)
{
    constexpr int K4 = KC / 4;
    extern __shared__ float smem_[];
    float* xs = smem_;             // [KC][68]
    float* ws = smem_ + KC * 68;   // [KC][68]
    const int tid = threadIdx.x;
    const int it  = blockIdx.x;
    const int ksp = it / g.jt_n;
    const int jt  = it - ksp * g.jt_n;
    const int j0  = jt << 6;
    const int k0  = ksp * KC;

    pdl_trigger();

    // W gather: independent of predecessor
    const int wofs = k0 + (k0 >= g.kjump_at ? g.kjump_ofs : 0);
    for (int idx = tid; idx < K4 * 64; idx += 256) {
        int k4 = idx & (K4 - 1), j = idx / K4;
        int jr = j0 + j;
        float4 v = make_float4(0.f, 0.f, 0.f, 0.f);
        if (jr < g.M) {
            const float* Wr = (jr < g.m1) ? (g.W1 + (size_t)jr * g.ldw)
                                          : (g.W2 + (size_t)(jr - g.m1) * g.ldw);
            int kk = k0 + (k4 << 2);
            if (kk + 3 < g.K) v = *reinterpret_cast<const float4*>(Wr + wofs + (k4 << 2));
            else {
                if (kk + 0 < g.K) v.x = Wr[wofs + (k4 << 2) + 0];
                if (kk + 1 < g.K) v.y = Wr[wofs + (k4 << 2) + 1];
                if (kk + 2 < g.K) v.z = Wr[wofs + (k4 << 2) + 2];
                if (kk + 3 < g.K) v.w = Wr[wofs + (k4 << 2) + 3];
            }
        }
        float* d = ws + (k4 << 2) * 68 + j;
        d[0] = v.x; d[68] = v.y; d[136] = v.z; d[204] = v.w;
    }

    pdl_wait();   // predecessor's outputs now visible

    for (int idx = tid; idx < K4 * 64; idx += 256) {
        int k4 = idx & (K4 - 1), n = idx / K4;
        int kk = k0 + (k4 << 2);
        float4 v = make_float4(0.f, 0.f, 0.f, 0.f);
        if (kk + 3 < g.K) v = xf.load4(n, kk);
        else {
            if (kk + 0 < g.K) v.x = xf.load1(n, kk + 0);
            if (kk + 1 < g.K) v.y = xf.load1(n, kk + 1);
            if (kk + 2 < g.K) v.z = xf.load1(n, kk + 2);
            if (kk + 3 < g.K) v.w = xf.load1(n, kk + 3);
        }
        float* d = xs + (k4 << 2) * 68 + n;
        d[0] = v.x; d[68] = v.y; d[136] = v.z; d[204] = v.w;
    }
    __syncthreads();

    const int tj = tid & 15, tn = tid >> 4;
    float acc[4][4];
#pragma unroll
    for (int a = 0; a < 4; a++)
#pragma unroll
        for (int b = 0; b < 4; b++) acc[a][b] = 0.f;

#pragma unroll 8
    for (int k = 0; k < KC; k++) {
        float4 wv = *reinterpret_cast<const float4*>(ws + k * 68 + tj * 4);
        float4 xv = *reinterpret_cast<const float4*>(xs + k * 68 + tn * 4);
        float xr[4] = {xv.x, xv.y, xv.z, xv.w};
        float wr[4] = {wv.x, wv.y, wv.z, wv.w};
#pragma unroll
        for (int jj = 0; jj < 4; jj++)
#pragma unroll
            for (int i = 0; i < 4; i++) acc[jj][i] += wr[jj] * xr[i];
    }

    if (j0 + tj * 4 < g.M) {
        float* base = g.P + (size_t)ksp * (64 * g.ldp) + j0 + tj * 4;
#pragma unroll
        for (int i = 0; i < 4; i++) {
            int n = tn * 4 + i;
            *reinterpret_cast<float4*>(base + (size_t)n * g.ldp) =
                make_float4(acc[0][i], acc[1][i], acc[2][i], acc[3][i]);
        }
    }
}

// ---------------- tiny reduce kernels (trigger at top, wait before partial reads) ----------------
__global__ __launch_bounds__(256) void k_xga(const float* __restrict__ pb2,
                                             const float* __restrict__ sv)
{
    pdl_trigger();
    int gid = blockIdx.x * 256 + threadIdx.x;      // 64*96 f4
    pdl_wait();
    if (gid >= 6144) return;
    int n = gid / 96, c4 = gid - n * 96;
    int c = c4 << 2;
    float4 v;
    if (c < 256) {
        v = *reinterpret_cast<const float4*>(pb2 + c);
#pragma unroll
        for (int sp = 0; sp < 8; sp++)
            add4(v, *reinterpret_cast<const float4*>(g_P + OFF_P2 + sp * 16384 + n * 256 + c));
        v.x = fmaxf(v.x, 0.f); v.y = fmaxf(v.y, 0.f);
        v.z = fmaxf(v.z, 0.f); v.w = fmaxf(v.w, 0.f);
    } else {
        v = *reinterpret_cast<const float4*>(sv + n * 128 + (c - 256));
    }
    *reinterpret_cast<float4*>(g_xga + n * 384 + c) = v;
}

__global__ __launch_bounds__(256) void k_oatt(const float* __restrict__ bih,
                                              const float* __restrict__ bhh)
{
    pdl_trigger();
    int gid = blockIdx.x * 256 + threadIdx.x;      // 64*128 f4
    pdl_wait();
    if (gid >= 8192) return;
    int n = gid >> 7, c = (gid & 127) << 2;
    float4 r = *reinterpret_cast<const float4*>(bih + c);
    float4 z = *reinterpret_cast<const float4*>(bih + 512 + c);
    float4 m = *reinterpret_cast<const float4*>(bih + 1024 + c);
#pragma unroll
    for (int sp = 0; sp < 12; sp++) {
        const float* q = g_P + OFF_A + (size_t)sp * 98304 + (size_t)n * 1536 + c;
        add4(r, *reinterpret_cast<const float4*>(q));
        add4(z, *reinterpret_cast<const float4*>(q + 512));
        add4(m, *reinterpret_cast<const float4*>(q + 1024));
    }
    float4 br = *reinterpret_cast<const float4*>(bhh + c);
    float4 bz = *reinterpret_cast<const float4*>(bhh + 512 + c);
    float4 bn = *reinterpret_cast<const float4*>(bhh + 1024 + c);
    float4 o;
    o.x = gru_out(r.x, z.x, m.x, br.x, bz.x, bn.x);
    o.y = gru_out(r.y, z.y, m.y, br.y, bz.y, bn.y);
    o.z = gru_out(r.z, z.z, m.z, br.z, bz.z, bn.z);
    o.w = gru_out(r.w, z.w, m.w, br.w, bz.w, bn.w);
    *reinterpret_cast<float4*>(g_oatt + n * 512 + c) = o;
}

__global__ __launch_bounds__(256) void k_attw(const float* __restrict__ bdec)
{
    pdl_trigger();
    int gid = blockIdx.x * 256 + threadIdx.x;      // 64*128 f4
    pdl_wait();
    if (gid >= 8192) return;
    int n = gid >> 7, c = (gid & 127) << 2;
    float4 s = *reinterpret_cast<const float4*>(bdec + c);
#pragma unroll
    for (int sp = 0; sp < 16; sp++)
        add4(s, *reinterpret_cast<const float4*>(g_P + OFF_W + sp * 32768 + n * 512 + c));
    *reinterpret_cast<float4*>(g_attW + n * 512 + c) = s;
}

__global__ __launch_bounds__(256) void k_odec(const float* __restrict__ sv,
                                              float* __restrict__ out)
{
    pdl_trigger();
    int gid = blockIdx.x * 256 + threadIdx.x;      // 64*288 f4
    pdl_wait();
    if (gid >= 18432) return;
    int n = gid / 288, c4 = gid - n * 288;
    int c = c4 << 2;
    float4 v;
    if (c < 512) {
        v = make_float4(0.f, 0.f, 0.f, 0.f);
        float w = 0.f;
#pragma unroll
        for (int sp = 0; sp < 8; sp++) {
            add4(v, *reinterpret_cast<const float4*>(g_part + (size_t)(n * 8 + sp) * 512 + c));
            w += g_wchunk[n * 8 + sp];
        }
        float inv = 1.f / fmaxf(w, 1e-12f);
        v.x *= inv; v.y *= inv; v.z *= inv; v.w *= inv;
        *reinterpret_cast<float4*>(out + 10240 + (size_t)n * 512 + c) = v;
    } else if (c < 1024) {
        v = *reinterpret_cast<const float4*>(g_oatt + n * 512 + (c - 512));
    } else {
        v = *reinterpret_cast<const float4*>(sv + n * 128 + (c - 1024));
    }
    *reinterpret_cast<float4*>(g_odec + n * 1152 + c) = v;
}

__global__ __launch_bounds__(256) void k_res1(const float* __restrict__ bsc,
                                              const float* __restrict__ bih,
                                              const float* __restrict__ bhh)
{
    pdl_trigger();
    int gid = blockIdx.x * 256 + threadIdx.x;      // 64*128 f4
    pdl_wait();
    if (gid >= 8192) return;
    int n = gid >> 7, c = (gid & 127) << 2;
    float4 sc = *reinterpret_cast<const float4*>(bsc + c);
    float4 r  = *reinterpret_cast<const float4*>(bih + c);
    float4 z  = *reinterpret_cast<const float4*>(bih + 512 + c);
    float4 m  = *reinterpret_cast<const float4*>(bih + 1024 + c);
#pragma unroll
    for (int sp = 0; sp < 18; sp++) {
        const float* pp = g_P + OFF_G + (size_t)sp * 131072 + (size_t)n * 2048;
        add4(sc, *reinterpret_cast<const float4*>(pp + c));
        add4(r,  *reinterpret_cast<const float4*>(pp + 512 + c));
        add4(z,  *reinterpret_cast<const float4*>(pp + 1024 + c));
        add4(m,  *reinterpret_cast<const float4*>(pp + 1536 + c));
    }
    float4 br = *reinterpret_cast<const float4*>(bhh + c);
    float4 bz = *reinterpret_cast<const float4*>(bhh + 512 + c);
    float4 bn = *reinterpret_cast<const float4*>(bhh + 1024 + c);
    float4 o;
    o.x = sc.x + gru_out(r.x, z.x, m.x, br.x, bz.x, bn.x);
    o.y = sc.y + gru_out(r.y, z.y, m.y, br.y, bz.y, bn.y);
    o.z = sc.z + gru_out(r.z, z.z, m.z, br.z, bz.z, bn.z);
    o.w = sc.w + gru_out(r.w, z.w, m.w, br.w, bz.w, bn.w);
    *reinterpret_cast<float4*>(g_res1 + n * 512 + c) = o;
}

// ---------------- fused attention: scores -> smem -> weighted sums ----------------
__global__ __launch_bounds__(256) void k_scoreattn(
    const float* __restrict__ encW, const float* __restrict__ enc,
    const float* __restrict__ wattn, const float* __restrict__ battn,
    const int* __restrict__ len)
{
    const int n = blockIdx.x >> 3, ch = blockIdx.x & 7;
    const int t0 = ch << 7;
    const int tid = threadIdx.x, lane = tid & 31, w = tid >> 5;

    pdl_trigger();

    __shared__ float aw[512], wv[512], we[128], wred[8];
    for (int c4 = tid; c4 < 128; c4 += 256) {
        int c = c4 << 2;
        *reinterpret_cast<float4*>(wv + c) = *reinterpret_cast<const float4*>(wattn + c);
    }
    const int rows = min(128, len[n] - t0);
    const float bat = battn[0];

    pdl_wait();   // attW ready

    if (rows <= 0) {
        *reinterpret_cast<float2*>(g_part + (size_t)(n * 8 + ch) * 512 + tid * 2) =
            make_float2(0.f, 0.f);
        if (tid == 0) g_wchunk[n * 8 + ch] = 0.f;
        return;
    }
    for (int c4 = tid; c4 < 128; c4 += 256) {
        int c = c4 << 2;
        *reinterpret_cast<float4*>(aw + c) = *reinterpret_cast<const float4*>(g_attW + n * 512 + c);
    }
    __syncthreads();

    // phase A: scores (warp w handles rows w*16 .. w*16+15)
    const float* base = encW + ((size_t)(n << 10) + t0) * 512;
    float wsum = 0.f;
    const int r0 = w * 16;
    const int r1 = min(r0 + 16, rows);
    for (int rr = r0; rr < r1; rr += 2) {
        const bool ok1 = (rr + 1 < r1);
        const float* rp = base + (size_t)rr * 512;
        float s0 = 0.f, s1 = 0.f;
#pragma unroll
        for (int q = 0; q < 4; q++) {
            int c = lane * 4 + q * 128;
            float4 v0 = *reinterpret_cast<const float4*>(rp + c);
            float4 v1 = ok1 ? *reinterpret_cast<const float4*>(rp + 512 + c)
                            : make_float4(0.f, 0.f, 0.f, 0.f);
            float4 a = *reinterpret_cast<const float4*>(aw + c);
            float4 wq = *reinterpret_cast<const float4*>(wv + c);
            s0 += tanh_fast(v0.x + a.x) * wq.x + tanh_fast(v0.y + a.y) * wq.y
                + tanh_fast(v0.z + a.z) * wq.z + tanh_fast(v0.w + a.w) * wq.w;
            s1 += tanh_fast(v1.x + a.x) * wq.x + tanh_fast(v1.y + a.y) * wq.y
                + tanh_fast(v1.z + a.z) * wq.z + tanh_fast(v1.w + a.w) * wq.w;
        }
#pragma unroll
        for (int o = 16; o > 0; o >>= 1) {
            s0 += __shfl_xor_sync(0xffffffffu, s0, o);
            s1 += __shfl_xor_sync(0xffffffffu, s1, o);
        }
        if (lane == 0) {
            float w0 = __expf(s0 + bat);
            we[rr] = w0; wsum += w0;
            if (ok1) { float w1 = __expf(s1 + bat); we[rr + 1] = w1; wsum += w1; }
        }
    }
    if (lane == 0) wred[w] = wsum;
    __syncthreads();
    if (tid == 0) {
        float s = 0.f;
#pragma unroll
        for (int i = 0; i < 8; i++) s += wred[i];
        g_wchunk[n * 8 + ch] = s;
    }

    // phase B: weighted column sums (thread = 2 cols)
    {
        const float* eb = enc + ((size_t)(n << 10) + t0) * 512 + tid * 2;
        float2 acc = make_float2(0.f, 0.f);
        int r = 0;
        for (; r + 16 <= rows; r += 16) {
            float wq[16]; float2 vv[16];
#pragma unroll
            for (int i = 0; i < 16; i++) {
                wq[i] = we[r + i];
                vv[i] = *reinterpret_cast<const float2*>(eb + (size_t)(r + i) * 512);
            }
#pragma unroll
            for (int i = 0; i < 16; i++) {
                acc.x += wq[i] * vv[i].x;
                acc.y += wq[i] * vv[i].y;
            }
        }
        for (; r < rows; r++) {
            float wq = we[r];
            float2 v = *reinterpret_cast<const float2*>(eb + (size_t)r * 512);
            acc.x += wq * v.x; acc.y += wq * v.y;
        }
        *reinterpret_cast<float2*>(g_part + (size_t)(n * 8 + ch) * 512 + tid * 2) = acc;
    }
}

// ---------------- final output reduce ----------------
__global__ __launch_bounds__(256) void k_out(const float* __restrict__ bout,
                                             float* __restrict__ out)
{
    pdl_trigger();
    int gid = blockIdx.x * 256 + threadIdx.x;
    pdl_wait();
    if (gid >= 10240) return;
    int n = gid / 160, j = gid - n * 160;
    float s = bout[j];
#pragma unroll
    for (int sp = 0; sp < 16; sp++) s += g_P[OFF_O + sp * 10240 + n * 160 + j];
    out[gid] = s;
}

// ---------------- host orchestration ----------------
template <class K, class... A>
static inline void pl(K kfn, int grid, int block, size_t smem, A... args)
{
    cudaLaunchConfig_t cfg;
    cfg.gridDim = dim3((unsigned)grid, 1, 1);
    cfg.blockDim = dim3((unsigned)block, 1, 1);
    cfg.dynamicSmemBytes = smem;
    cfg.stream = 0;
    static cudaLaunchAttribute at[1];
    at[0].id = cudaLaunchAttributeProgrammaticStreamSerialization;
    at[0].val.programmaticStreamSerializationAllowed = 1;
    cfg.attrs = at;
    cfg.numAttrs = 1;
    cudaLaunchKernelEx(&cfg, kfn, args...);
}

extern "C" void kernel_launch(void* const* d_in, const int* in_sizes, int n_in,
                              void* d_out, int out_size)
{
    (void)n_in; (void)out_size;
    bool dictord = (in_sizes[4] == 64);
    int b = dictord ? 5 : 4;

    const float* enc   = (const float*)d_in[0];
    const float* encW  = (const float*)d_in[1];
    const float* dec   = (const float*)d_in[2];
    const float* sv    = (const float*)d_in[3];
    const int*   len   = (const int*)(dictord ? d_in[4] : d_in[28]);
    const float* pw1   = (const float*)d_in[b + 0];
    const float* pb1   = (const float*)d_in[b + 1];
    const float* pw2   = (const float*)d_in[b + 2];
    const float* pb2   = (const float*)d_in[b + 3];
    const float* wdec_ = (const float*)d_in[b + 4];
    const float* bdec  = (const float*)d_in[b + 5];
    const float* ga_ih = (const float*)d_in[b + 6];
    const float* ga_bih= (const float*)d_in[b + 8];
    const float* ga_bhh= (const float*)d_in[b + 9];
    const float* wattn = (const float*)d_in[b + 10];
    const float* battn = (const float*)d_in[b + 11];
    const float* wsc   = (const float*)d_in[b + 12];
    const float* bsc   = (const float*)d_in[b + 13];
    const float* g1_ih = (const float*)d_in[b + 14];
    const float* g1_bih= (const float*)d_in[b + 16];
    const float* g1_bhh= (const float*)d_in[b + 17];
    const float* g2_ih = (const float*)d_in[b + 18];
    const float* g2_bih= (const float*)d_in[b + 20];
    const float* g2_bhh= (const float*)d_in[b + 21];
    const float* wout_ = (const float*)d_in[b + 22];
    const float* bout  = (const float*)d_in[b + 23];
    float* out = (float*)d_out;

    float *P, *xga, *oatt, *odec, *res1;
    cudaGetSymbolAddress((void**)&P,    g_P);
    cudaGetSymbolAddress((void**)&xga,  g_xga);
    cudaGetSymbolAddress((void**)&oatt, g_oatt);
    cudaGetSymbolAddress((void**)&odec, g_odec);
    cudaGetSymbolAddress((void**)&res1, g_res1);

    static bool attr_set = false;
    if (!attr_set) {
        cudaFuncSetAttribute(k_gemm<32, XDirect>,  cudaFuncAttributeMaxDynamicSharedMemorySize, 17408);
        cudaFuncSetAttribute(k_gemm<32, XGru2Red>, cudaFuncAttributeMaxDynamicSharedMemorySize, 17408);
        cudaFuncSetAttribute(k_gemm<64, XDirect>,  cudaFuncAttributeMaxDynamicSharedMemorySize, 34816);
        cudaFuncSetAttribute(k_gemm<64, XPre1Red>, cudaFuncAttributeMaxDynamicSharedMemorySize, 34816);
        attr_set = true;
    }

    const int BIGJ = 1 << 30;

    // 1. pre1 partials (M=512, K=80, KC=64, jt=8, ks=2) -> 16 blocks
    pl(k_gemm<64, XDirect>, 16, 256, 34816, XDirect{dec, 80},
       GW{pw1, BIGJ, pw1, 80, BIGJ, 0, 512, 80, 8, P + OFF_P1, 512});
    // 2. pre2 partials (M=256, K=512, KC=64, jt=4, ks=8) -> 32 blocks
    pl(k_gemm<64, XPre1Red>, 32, 256, 34816, XPre1Red{P + OFF_P1, pb1},
       GW{pw2, BIGJ, pw2, 512, BIGJ, 0, 256, 512, 4, P + OFF_P2, 256});
    // 3. xga = [relu(pre2) | sv]
    pl(k_xga, 24, 256, 0, pb2, sv);
    // 4. gruA partials (M=1536, K=384, KC=32, jt=24, ks=12), W col jump at 256 -> 288 blocks
    pl(k_gemm<32, XDirect>, 288, 256, 17408, XDirect{xga, 384},
       GW{ga_ih, BIGJ, ga_ih, 896, 256, 512, 1536, 384, 24, P + OFF_A, 1536});
    // 5. oatt = gruA reduce
    pl(k_oatt, 32, 256, 0, ga_bih, ga_bhh);
    // 6. wdec partials (M=512, K=512, KC=32, jt=8, ks=16) -> 128 blocks
    pl(k_gemm<32, XDirect>, 128, 256, 17408, XDirect{oatt, 512},
       GW{wdec_, BIGJ, wdec_, 512, BIGJ, 0, 512, 512, 8, P + OFF_W, 512});
    // 7. attW materialize
    pl(k_attw, 32, 256, 0, bdec);
    // 8. fused attention (512 blocks)
    pl(k_scoreattn, 512, 256, 0, encW, enc, wattn, battn, len);
    // 9. odec materialize + attn output write
    pl(k_odec, 72, 256, 0, sv, out);
    // 10. fused wsc|g1 partials (M=2048, K=1152, KC=64, jt=32, ks=18) -> 576 blocks
    pl(k_gemm<64, XDirect>, 576, 256, 34816, XDirect{odec, 1152},
       GW{wsc, 512, g1_ih, 1152, BIGJ, 0, 2048, 1152, 32, P + OFF_G, 2048});
    // 11. res1 reduce
    pl(k_res1, 32, 256, 0, bsc, g1_bih, g1_bhh);
    // 12. g2 partials (M=1536, K=512, KC=32, jt=24, ks=16) -> 384 blocks
    pl(k_gemm<32, XDirect>, 384, 256, 17408, XDirect{res1, 512},
       GW{g2_ih, BIGJ, g2_ih, 512, BIGJ, 0, 1536, 512, 24, P + OFF_2, 1536});
    // 13. wout partials (M=160, K=512, KC=32, jt=3, ks=16); X = res1 + gru2 -> 48 blocks
    pl(k_gemm<32, XGru2Red>, 48, 256, 17408, XGru2Red{P + OFF_2, g2_bih, g2_bhh, res1},
       GW{wout_, BIGJ, wout_, 512, BIGJ, 0, 160, 512, 3, P + OFF_O, 160});
    // 14. output reduce (40 blocks)
    pl(k_out, 40, 256, 0, bout, out);
}